// round 13
// baseline (speedup 1.0000x reference)
#include <cuda_runtime.h>
#include <cuda_fp16.h>
#include <stdint.h>
#include <math.h>

#define Bb 32
#define Cc 256
#define Hh 64
#define Ww 64
#define HW 4096
#define NTOT (Bb*Cc*HW)

typedef unsigned int u32;

// Scratch (allocation-free rule: __device__ globals)
__device__ __half g_mid[NTOT];         // 64 MB: dwconv output, fp16
__device__ __half g_wh[Cc*Cc];         // pointwise W, fp16
__device__ __half g_yh[NTOT];          // 64 MB: post-pointwise+pwbn, fp16
__device__ float g_ssq[Bb*Cc];         // per-(b,c) sum of squares

__device__ __forceinline__ float gelu_f(float v) {
    return 0.5f * v * (1.0f + erff(v * 0.7071067811865475f));
}

// Fast GELU: Abramowitz-Stegun 7.1.25 erf (3-term, |eps| <= 2.5e-5 abs).
__device__ __forceinline__ float gelu_fast(float v) {
    const float az = fabsf(v) * 0.7071067811865475f;
    const float t  = __fdividef(1.0f, fmaf(0.47047f, az, 1.0f));
    const float e  = __expf(-az * az);
    float p = fmaf(t, 0.7478556f, -0.0958798f);
    p = fmaf(t, p, 0.3480242f);
    p *= t;
    const float erfabs = fmaf(-p, e, 1.0f);
    return 0.5f * fmaf(fabsf(v), erfabs, v);
}

__device__ __forceinline__ u32 smem_u32(const void* p) {
    return (u32)__cvta_generic_to_shared(p);
}

__device__ __forceinline__ void ldsm_x4(u32& r0, u32& r1, u32& r2, u32& r3, u32 a) {
    asm volatile("ldmatrix.sync.aligned.m8n8.x4.shared.b16 {%0,%1,%2,%3},[%4];\n"
                 : "=r"(r0), "=r"(r1), "=r"(r2), "=r"(r3) : "r"(a));
}
__device__ __forceinline__ void ldsm_x4t(u32& r0, u32& r1, u32& r2, u32& r3, u32 a) {
    asm volatile("ldmatrix.sync.aligned.m8n8.x4.trans.shared.b16 {%0,%1,%2,%3},[%4];\n"
                 : "=r"(r0), "=r"(r1), "=r"(r2), "=r"(r3) : "r"(a));
}
__device__ __forceinline__ void mma_f16(float* c, const u32* a, const u32* bq) {
    asm volatile(
        "mma.sync.aligned.m16n8k16.row.col.f32.f16.f16.f32 "
        "{%0,%1,%2,%3},{%4,%5,%6,%7},{%8,%9},{%0,%1,%2,%3};\n"
        : "+f"(c[0]), "+f"(c[1]), "+f"(c[2]), "+f"(c[3])
        : "r"(a[0]), "r"(a[1]), "r"(a[2]), "r"(a[3]), "r"(bq[0]), "r"(bq[1]));
}

#define CP_ASYNC16(dst, src) \
    asm volatile("cp.async.cg.shared.global [%0], [%1], 16;" :: "r"(dst), "l"(src))
#define CP_COMMIT() asm volatile("cp.async.commit_group;" ::: "memory")

// ---------------------------------------------------------------------------
// K1: fused dwconv(3,5,7) + BN + GELU + average -> g_mid (fp16)
// One block per (b,c) plane. 70x70 haloed fp32 tile in smem.
// Vertical register blocking: each thread owns a 4-row x 4-col output patch
// and slides ONCE over its 10 input rows (each row loaded a single time).
// Blocks 0..255 also convert pointwise W to fp16. Also zeroes g_ssq.
// ---------------------------------------------------------------------------
__global__ __launch_bounds__(256) void k_dwconv(
    const float* __restrict__ x,
    const float* __restrict__ w3,
    const float* __restrict__ b3w, const float* __restrict__ b3b,
    const float* __restrict__ b3m, const float* __restrict__ b3v,
    const float* __restrict__ w5,
    const float* __restrict__ b5w, const float* __restrict__ b5b,
    const float* __restrict__ b5m, const float* __restrict__ b5v,
    const float* __restrict__ w7,
    const float* __restrict__ b7w, const float* __restrict__ b7b,
    const float* __restrict__ b7m, const float* __restrict__ b7v,
    const float* __restrict__ pw)
{
    __shared__ float tile[70 * 72];
    __shared__ float sw3[9], sw5[25], sw7[49];

    const int blk = blockIdx.x;        // b*256 + c
    const int c   = blk & 255;
    const int tid = threadIdx.x;

    if (tid == 0) g_ssq[blk] = 0.0f;

    // fold-in: blocks 0..255 convert the pointwise weight (one 256-chunk each)
    if (blk < 256) {
        int i = blk * 256 + tid;
        g_wh[i] = __float2half(pw[i]);
    }

    const float* __restrict__ xp = x + (size_t)blk * HW;

    if (tid < 9)        sw3[tid]      = w3[c * 9 + tid];
    else if (tid < 34)  sw5[tid - 9]  = w5[c * 25 + (tid - 9)];
    else if (tid < 83)  sw7[tid - 34] = w7[c * 49 + (tid - 34)];

    for (int idx = tid; idx < 70 * 70; idx += 256) {
        int sy = idx / 70, sx = idx - sy * 70;
        int gy = sy - 3, gx = sx - 3;
        float v = 0.0f;
        if ((unsigned)gy < 64u && (unsigned)gx < 64u) v = xp[gy * 64 + gx];
        tile[sy * 72 + sx] = v;
    }

    const float sc3 = b3w[c] * rsqrtf(b3v[c] + 1e-5f);
    const float sh3 = b3b[c] - b3m[c] * sc3;
    const float sc5 = b5w[c] * rsqrtf(b5v[c] + 1e-5f);
    const float sh5 = b5b[c] - b5m[c] * sc5;
    const float sc7 = b7w[c] * rsqrtf(b7v[c] + 1e-5f);
    const float sh7 = b7b[c] - b7m[c] * sc7;

    __syncthreads();

    const int px0 = (tid & 15) * 4;    // output col base
    const int y0  = (tid >> 4) * 4;    // output row base (0..60)
    const float inv3 = (1.0f / 3.0f);

    float a7[4][4], a5[4][4], a3[4][4];
    #pragma unroll
    for (int j = 0; j < 4; j++)
        #pragma unroll
        for (int cc = 0; cc < 4; cc++) { a7[j][cc] = 0.f; a5[j][cc] = 0.f; a3[j][cc] = 0.f; }

    // single vertical sweep over the 10 input rows this patch needs
    #pragma unroll
    for (int r = 0; r < 10; r++) {
        const float* rowp = &tile[(y0 + r) * 72 + px0];
        float4 v0 = *(const float4*)(rowp);
        float4 v1 = *(const float4*)(rowp + 4);
        float4 v2 = *(const float4*)(rowp + 8);
        float f[12];
        f[0]=v0.x; f[1]=v0.y; f[2]=v0.z; f[3]=v0.w;
        f[4]=v1.x; f[5]=v1.y; f[6]=v1.z; f[7]=v1.w;
        f[8]=v2.x; f[9]=v2.y; f[10]=v2.z; f[11]=v2.w;

        #pragma unroll
        for (int j = 0; j < 4; j++) {
            const int d = r - j;               // compile-time per (r,j)
            if (d >= 0 && d <= 6) {            // 7x7 tap row
                #pragma unroll
                for (int kx = 0; kx < 7; kx++) {
                    const float w = sw7[d * 7 + kx];
                    #pragma unroll
                    for (int cc = 0; cc < 4; cc++) a7[j][cc] += f[cc + kx] * w;
                }
            }
            if (d >= 1 && d <= 5) {            // 5x5 tap row
                #pragma unroll
                for (int kx = 0; kx < 5; kx++) {
                    const float w = sw5[(d - 1) * 5 + kx];
                    #pragma unroll
                    for (int cc = 0; cc < 4; cc++) a5[j][cc] += f[cc + 1 + kx] * w;
                }
            }
            if (d >= 2 && d <= 4) {            // 3x3 tap row
                #pragma unroll
                for (int kx = 0; kx < 3; kx++) {
                    const float w = sw3[(d - 2) * 3 + kx];
                    #pragma unroll
                    for (int cc = 0; cc < 4; cc++) a3[j][cc] += f[cc + 2 + kx] * w;
                }
            }
        }
    }

    // epilogue: BN + gelu + avg + fp16 store, one row at a time
    #pragma unroll
    for (int j = 0; j < 4; j++) {
        __half hh[4];
        #pragma unroll
        for (int cc = 0; cc < 4; cc++) {
            float v = gelu_fast(a3[j][cc] * sc3 + sh3)
                    + gelu_fast(a5[j][cc] * sc5 + sh5)
                    + gelu_fast(a7[j][cc] * sc7 + sh7);
            hh[cc] = __float2half(v * inv3);
        }
        size_t off = (size_t)blk * HW + (y0 + j) * 64 + px0;
        ((__half2*)&g_mid[off])[0] = __halves2half2(hh[0], hh[1]);
        ((__half2*)&g_mid[off])[1] = __halves2half2(hh[2], hh[3]);
    }
}

// ---------------------------------------------------------------------------
// K2: mma.sync fp16 GEMM, single term, 3-stage cp.async pipeline.
// Block tile 128(M=o) x 128(N=p), BK=32. 8 warps: 2(M) x 4(N).
// Fused pwbn + ssq; smem-staged coalesced fp16 y stores. (R9/R12, unchanged)
// ---------------------------------------------------------------------------
#define AS_OFF(st, m, k) ((st) * (128*40) + (m)*40 + (k))
#define BS_OFF(st, k, n) (15360 + (st)*(32*136) + (k)*136 + (n))
#define K2_DYNSMEM ((15360 + 13056) * 2)

__global__ __launch_bounds__(256) void k_pwgemm(
    const float* __restrict__ pbw, const float* __restrict__ pbb,
    const float* __restrict__ pbm, const float* __restrict__ pbv)
{
    extern __shared__ __half sm[];

    const int b     = blockIdx.z;
    const int nBase = blockIdx.x * 128;
    const int mBase = blockIdx.y * 128;

    const int tid  = threadIdx.x;
    const int lane = tid & 31;
    const int warp = tid >> 5;
    const int warp_m = warp >> 2;
    const int warp_n = warp & 3;

    const __half* __restrict__ Mb = g_mid + (size_t)b * Cc * HW;

    float acc[4][4][4];
    #pragma unroll
    for (int i = 0; i < 4; i++)
        #pragma unroll
        for (int j = 0; j < 4; j++)
            #pragma unroll
            for (int q = 0; q < 4; q++) acc[i][j][q] = 0.0f;

    auto issue = [&](int st, int k0) {
        #pragma unroll
        for (int i = 0; i < 2; i++) {
            int e = i * 256 + tid;
            int row = e >> 2, seg = e & 3;
            CP_ASYNC16(smem_u32(&sm[AS_OFF(st, row, seg * 8)]),
                       &g_wh[(size_t)(mBase + row) * 256 + k0 + seg * 8]);
        }
        #pragma unroll
        for (int i = 0; i < 2; i++) {
            int e = i * 256 + tid;
            int row = e >> 4, seg = e & 15;
            CP_ASYNC16(smem_u32(&sm[BS_OFF(st, row, seg * 8)]),
                       &Mb[(size_t)(k0 + row) * HW + nBase + seg * 8]);
        }
    };

    issue(0, 0);
    CP_COMMIT();
    issue(1, 32);
    CP_COMMIT();

    for (int s = 0; s < 8; s++) {
        if (s < 7) {
            asm volatile("cp.async.wait_group 1;" ::: "memory");
        } else {
            asm volatile("cp.async.wait_group 0;" ::: "memory");
        }
        __syncthreads();

        const int st = s % 3;
        #pragma unroll
        for (int ks = 0; ks < 32; ks += 16) {
            u32 ah[4][4];
            const int a_m = warp_m * 64 + (lane & 15);
            const int a_k = ks + ((lane >> 4) << 3);
            #pragma unroll
            for (int fm = 0; fm < 4; fm++) {
                ldsm_x4(ah[fm][0], ah[fm][1], ah[fm][2], ah[fm][3],
                        smem_u32(&sm[AS_OFF(st, a_m + fm * 16, a_k)]));
            }
            u32 bq[4][2];
            const int b_k = ks + (lane & 15);
            const int b_n = warp_n * 32 + ((lane >> 4) << 3);
            #pragma unroll
            for (int g = 0; g < 2; g++) {
                u32 r0, r1, r2, r3;
                ldsm_x4t(r0, r1, r2, r3,
                         smem_u32(&sm[BS_OFF(st, b_k, b_n + g * 16)]));
                bq[g*2][0] = r0; bq[g*2][1] = r1;
                bq[g*2+1][0] = r2; bq[g*2+1][1] = r3;
            }
            #pragma unroll
            for (int fm = 0; fm < 4; fm++)
                #pragma unroll
                for (int fn = 0; fn < 4; fn++)
                    mma_f16(acc[fm][fn], ah[fm], bq[fn]);
        }

        if (s + 2 < 8) {
            issue((s + 2) % 3, (s + 2) * 32);
            CP_COMMIT();
        }
    }

    __syncthreads();
    __half* s_y = sm;  // 128 x 136 halves

    const int row  = lane >> 2;
    const int colq = (lane & 3) * 2;

    #pragma unroll
    for (int fm = 0; fm < 4; fm++) {
        const int o0 = mBase + warp_m * 64 + fm * 16 + row;
        const int o1 = o0 + 8;
        const int l0 = warp_m * 64 + fm * 16 + row;
        const float sc0 = pbw[o0] * rsqrtf(pbv[o0] + 1e-5f);
        const float sh0 = pbb[o0] - pbm[o0] * sc0;
        const float sc1 = pbw[o1] * rsqrtf(pbv[o1] + 1e-5f);
        const float sh1 = pbb[o1] - pbm[o1] * sc1;
        float ss0 = 0.0f, ss1 = 0.0f;
        #pragma unroll
        for (int fn = 0; fn < 4; fn++) {
            const int pl = warp_n * 32 + fn * 8 + colq;
            float v0 = acc[fm][fn][0] * sc0 + sh0;
            float v1 = acc[fm][fn][1] * sc0 + sh0;
            float v2 = acc[fm][fn][2] * sc1 + sh1;
            float v3 = acc[fm][fn][3] * sc1 + sh1;
            ss0 += v0 * v0 + v1 * v1;
            ss1 += v2 * v2 + v3 * v3;
            *(__half2*)&s_y[l0 * 136 + pl] =
                __halves2half2(__float2half(v0), __float2half(v1));
            *(__half2*)&s_y[(l0 + 8) * 136 + pl] =
                __halves2half2(__float2half(v2), __float2half(v3));
        }
        ss0 += __shfl_xor_sync(0xffffffffu, ss0, 1);
        ss0 += __shfl_xor_sync(0xffffffffu, ss0, 2);
        ss1 += __shfl_xor_sync(0xffffffffu, ss1, 1);
        ss1 += __shfl_xor_sync(0xffffffffu, ss1, 2);
        if ((lane & 3) == 0) {
            atomicAdd(&g_ssq[b * Cc + o0], ss0);
            atomicAdd(&g_ssq[b * Cc + o1], ss1);
        }
    }
    __syncthreads();

    __half* __restrict__ yb = g_yh + (size_t)b * Cc * HW;
    #pragma unroll
    for (int k = 0; k < 16; k++) {
        const int r = warp + k * 8;
        uint2 v = *(const uint2*)&s_y[r * 136 + lane * 4];
        *(uint2*)&yb[(size_t)(mBase + r) * HW + nBase + lane * 4] = v;
    }
}

// ---------------------------------------------------------------------------
// K4: fused GRN + final. One block per (b,c): reduce Gx over channels
// (redundant per block), then out = gelu(yh * a + beta[c] + x).
// ---------------------------------------------------------------------------
__global__ __launch_bounds__(256) void k_final(
    const float* __restrict__ x,
    const float* __restrict__ gamma,
    const float* __restrict__ beta,
    float* __restrict__ out)
{
    __shared__ float sh[256];

    const int bc = blockIdx.x;          // b*256 + c
    const int b  = bc >> 8;
    const int c  = bc & 255;
    const int tid = threadIdx.x;

    const float Gx_t = sqrtf(g_ssq[b * Cc + tid]);
    sh[tid] = Gx_t;
    __syncthreads();
    #pragma unroll
    for (int s = 128; s > 0; s >>= 1) {
        if (tid < s) sh[tid] += sh[tid + s];
        __syncthreads();
    }
    const float mean = sh[0] * (1.0f / 256.0f);
    const float Gx   = sqrtf(g_ssq[bc]);
    const float a    = 1.0f + gamma[c] * (Gx / (mean + 1e-6f));
    const float bt   = beta[c];

    const __half2* yp = (const __half2*)(g_yh + (size_t)bc * HW);
    const float4*  xp = (const float4*)(x + (size_t)bc * HW);
    float4*        op = (float4*)(out + (size_t)bc * HW);

    #pragma unroll
    for (int k = 0; k < 4; k++) {
        const int i4 = k * 256 + tid;
        __half2 y01 = yp[i4 * 2];
        __half2 y23 = yp[i4 * 2 + 1];
        float2 f01 = __half22float2(y01);
        float2 f23 = __half22float2(y23);
        float4 xv = xp[i4];
        float4 ov;
        ov.x = gelu_f(f01.x * a + bt + xv.x);
        ov.y = gelu_f(f01.y * a + bt + xv.y);
        ov.z = gelu_f(f23.x * a + bt + xv.z);
        ov.w = gelu_f(f23.y * a + bt + xv.w);
        op[i4] = ov;
    }
}

// ---------------------------------------------------------------------------
extern "C" void kernel_launch(void* const* d_in, const int* in_sizes, int n_in,
                              void* d_out, int out_size)
{
    const float* x    = (const float*)d_in[0];
    const float* w3   = (const float*)d_in[1];
    const float* b3w  = (const float*)d_in[2];
    const float* b3b  = (const float*)d_in[3];
    const float* b3m  = (const float*)d_in[4];
    const float* b3v  = (const float*)d_in[5];
    const float* w5   = (const float*)d_in[6];
    const float* b5w  = (const float*)d_in[7];
    const float* b5b  = (const float*)d_in[8];
    const float* b5m  = (const float*)d_in[9];
    const float* b5v  = (const float*)d_in[10];
    const float* w7   = (const float*)d_in[11];
    const float* b7w  = (const float*)d_in[12];
    const float* b7b  = (const float*)d_in[13];
    const float* b7m  = (const float*)d_in[14];
    const float* b7v  = (const float*)d_in[15];
    const float* pw   = (const float*)d_in[16];
    const float* pbw  = (const float*)d_in[17];
    const float* pbb  = (const float*)d_in[18];
    const float* pbm  = (const float*)d_in[19];
    const float* pbv  = (const float*)d_in[20];
    const float* grng = (const float*)d_in[21];
    const float* grnb = (const float*)d_in[22];

    cudaFuncSetAttribute(k_pwgemm,
                         cudaFuncAttributeMaxDynamicSharedMemorySize, K2_DYNSMEM);

    k_dwconv<<<Bb * Cc, 256>>>(x, w3, b3w, b3b, b3m, b3v,
                               w5, b5w, b5b, b5m, b5v,
                               w7, b7w, b7b, b7m, b7v, pw);

    dim3 g2(HW / 128, Cc / 128, Bb);   // (32, 2, 32)
    k_pwgemm<<<g2, 256, K2_DYNSMEM>>>(pbw, pbb, pbm, pbv);

    k_final<<<Bb * Cc, 256>>>(x, grng, grnb, (float*)d_out);
}

// round 14
// speedup vs baseline: 1.0088x; 1.0088x over previous
#include <cuda_runtime.h>
#include <cuda_fp16.h>
#include <stdint.h>
#include <math.h>

#define Bb 32
#define Cc 256
#define Hh 64
#define Ww 64
#define HW 4096
#define NTOT (Bb*Cc*HW)

typedef unsigned int u32;

// Scratch (allocation-free rule: __device__ globals)
__device__ __half g_mid[NTOT];         // 64 MB: dwconv output, fp16
__device__ __half g_wh[Cc*Cc];         // pointwise W, fp16
__device__ __half g_yh[NTOT];          // 64 MB: post-pointwise+pwbn, fp16
__device__ float g_ssq[Bb*Cc];         // per-(b,c) sum of squares

__device__ __forceinline__ float gelu_f(float v) {
    return 0.5f * v * (1.0f + erff(v * 0.7071067811865475f));
}

// Fast GELU: Abramowitz-Stegun 7.1.25 erf (3-term, |eps| <= 2.5e-5 abs).
__device__ __forceinline__ float gelu_fast(float v) {
    const float az = fabsf(v) * 0.7071067811865475f;
    const float t  = __fdividef(1.0f, fmaf(0.47047f, az, 1.0f));
    const float e  = __expf(-az * az);
    float p = fmaf(t, 0.7478556f, -0.0958798f);
    p = fmaf(t, p, 0.3480242f);
    p *= t;
    const float erfabs = fmaf(-p, e, 1.0f);
    return 0.5f * fmaf(fabsf(v), erfabs, v);
}

__device__ __forceinline__ u32 smem_u32(const void* p) {
    return (u32)__cvta_generic_to_shared(p);
}

__device__ __forceinline__ void ldsm_x4(u32& r0, u32& r1, u32& r2, u32& r3, u32 a) {
    asm volatile("ldmatrix.sync.aligned.m8n8.x4.shared.b16 {%0,%1,%2,%3},[%4];\n"
                 : "=r"(r0), "=r"(r1), "=r"(r2), "=r"(r3) : "r"(a));
}
__device__ __forceinline__ void ldsm_x4t(u32& r0, u32& r1, u32& r2, u32& r3, u32 a) {
    asm volatile("ldmatrix.sync.aligned.m8n8.x4.trans.shared.b16 {%0,%1,%2,%3},[%4];\n"
                 : "=r"(r0), "=r"(r1), "=r"(r2), "=r"(r3) : "r"(a));
}
__device__ __forceinline__ void mma_f16(float* c, const u32* a, const u32* bq) {
    asm volatile(
        "mma.sync.aligned.m16n8k16.row.col.f32.f16.f16.f32 "
        "{%0,%1,%2,%3},{%4,%5,%6,%7},{%8,%9},{%0,%1,%2,%3};\n"
        : "+f"(c[0]), "+f"(c[1]), "+f"(c[2]), "+f"(c[3])
        : "r"(a[0]), "r"(a[1]), "r"(a[2]), "r"(a[3]), "r"(bq[0]), "r"(bq[1]));
}

#define CP_ASYNC16(dst, src) \
    asm volatile("cp.async.cg.shared.global [%0], [%1], 16;" :: "r"(dst), "l"(src))
#define CP_COMMIT() asm volatile("cp.async.commit_group;" ::: "memory")

// ---------------------------------------------------------------------------
// K1: fused dwconv(3,5,7) + BN + GELU + average -> g_mid (fp16)
// (R12 version — measured at ~88% of the scalar-FFMA roofline; frozen.)
// ---------------------------------------------------------------------------
__global__ __launch_bounds__(256) void k_dwconv(
    const float* __restrict__ x,
    const float* __restrict__ w3,
    const float* __restrict__ b3w, const float* __restrict__ b3b,
    const float* __restrict__ b3m, const float* __restrict__ b3v,
    const float* __restrict__ w5,
    const float* __restrict__ b5w, const float* __restrict__ b5b,
    const float* __restrict__ b5m, const float* __restrict__ b5v,
    const float* __restrict__ w7,
    const float* __restrict__ b7w, const float* __restrict__ b7b,
    const float* __restrict__ b7m, const float* __restrict__ b7v,
    const float* __restrict__ pw)
{
    __shared__ float tile[70 * 72];
    __shared__ float sw3[9], sw5[25], sw7[49];

    const int blk = blockIdx.x;        // b*256 + c
    const int c   = blk & 255;
    const int tid = threadIdx.x;

    if (tid == 0) g_ssq[blk] = 0.0f;

    if (blk < 256) {
        int i = blk * 256 + tid;
        g_wh[i] = __float2half(pw[i]);
    }

    const float* __restrict__ xp = x + (size_t)blk * HW;

    if (tid < 9)        sw3[tid]      = w3[c * 9 + tid];
    else if (tid < 34)  sw5[tid - 9]  = w5[c * 25 + (tid - 9)];
    else if (tid < 83)  sw7[tid - 34] = w7[c * 49 + (tid - 34)];

    for (int idx = tid; idx < 70 * 70; idx += 256) {
        int sy = idx / 70, sx = idx - sy * 70;
        int gy = sy - 3, gx = sx - 3;
        float v = 0.0f;
        if ((unsigned)gy < 64u && (unsigned)gx < 64u) v = xp[gy * 64 + gx];
        tile[sy * 72 + sx] = v;
    }

    const float sc3 = b3w[c] * rsqrtf(b3v[c] + 1e-5f);
    const float sh3 = b3b[c] - b3m[c] * sc3;
    const float sc5 = b5w[c] * rsqrtf(b5v[c] + 1e-5f);
    const float sh5 = b5b[c] - b5m[c] * sc5;
    const float sc7 = b7w[c] * rsqrtf(b7v[c] + 1e-5f);
    const float sh7 = b7b[c] - b7m[c] * sc7;

    __syncthreads();

    const int tx = tid & 15;
    const int r0 = tid >> 4;
    const float inv3 = (1.0f / 3.0f);

    #pragma unroll
    for (int rit = 0; rit < 4; rit++) {
        const int y = r0 + rit * 16;
        float a3[4] = {0.f, 0.f, 0.f, 0.f};
        float a5[4] = {0.f, 0.f, 0.f, 0.f};
        float a7[4] = {0.f, 0.f, 0.f, 0.f};

        #pragma unroll
        for (int ky = 0; ky < 7; ky++) {
            const float* rowp = &tile[(y + ky) * 72 + tx * 4];
            float4 v0 = *(const float4*)(rowp);
            float4 v1 = *(const float4*)(rowp + 4);
            float4 v2 = *(const float4*)(rowp + 8);
            float f[12];
            f[0]=v0.x; f[1]=v0.y; f[2]=v0.z; f[3]=v0.w;
            f[4]=v1.x; f[5]=v1.y; f[6]=v1.z; f[7]=v1.w;
            f[8]=v2.x; f[9]=v2.y; f[10]=v2.z; f[11]=v2.w;

            #pragma unroll
            for (int kx = 0; kx < 7; kx++) {
                const float w = sw7[ky * 7 + kx];
                #pragma unroll
                for (int j = 0; j < 4; j++) a7[j] += f[j + kx] * w;
            }
            if (ky >= 1 && ky <= 5) {
                #pragma unroll
                for (int kx = 0; kx < 5; kx++) {
                    const float w = sw5[(ky - 1) * 5 + kx];
                    #pragma unroll
                    for (int j = 0; j < 4; j++) a5[j] += f[j + 1 + kx] * w;
                }
            }
            if (ky >= 2 && ky <= 4) {
                #pragma unroll
                for (int kx = 0; kx < 3; kx++) {
                    const float w = sw3[(ky - 2) * 3 + kx];
                    #pragma unroll
                    for (int j = 0; j < 4; j++) a3[j] += f[j + 2 + kx] * w;
                }
            }
        }

        __half hh[4];
        #pragma unroll
        for (int j = 0; j < 4; j++) {
            float v = gelu_fast(a3[j] * sc3 + sh3)
                    + gelu_fast(a5[j] * sc5 + sh5)
                    + gelu_fast(a7[j] * sc7 + sh7);
            hh[j] = __float2half(v * inv3);
        }
        size_t off = (size_t)blk * HW + y * 64 + tx * 4;
        ((__half2*)&g_mid[off])[0] = __halves2half2(hh[0], hh[1]);
        ((__half2*)&g_mid[off])[1] = __halves2half2(hh[2], hh[3]);
    }
}

// ---------------------------------------------------------------------------
// K2: mma.sync fp16 GEMM, M=256 (all o) x N=64 tile, BK=32, 3-stage cp.async.
// mid read from DRAM exactly ONCE. 8 warps: 4(M) x 2(N), warp tile 64x32.
// Fused pwbn + ssq; smem-staged coalesced fp16 y stores.
// ---------------------------------------------------------------------------
// smem (halves): As[3][256][40] = 30720; Bs[3][32][72] = 6912; total 37632
#define AS_OFF(st, m, k) ((st) * (256*40) + (m)*40 + (k))
#define BS_OFF(st, k, n) (30720 + (st)*(32*72) + (k)*72 + (n))
#define K2_DYNSMEM (37632 * 2)

__global__ __launch_bounds__(256) void k_pwgemm(
    const float* __restrict__ pbw, const float* __restrict__ pbb,
    const float* __restrict__ pbm, const float* __restrict__ pbv)
{
    extern __shared__ __half sm[];

    const int b     = blockIdx.z;
    const int nBase = blockIdx.x * 64;

    const int tid  = threadIdx.x;
    const int lane = tid & 31;
    const int warp = tid >> 5;
    const int warp_m = warp >> 1;          // 0..3
    const int warp_n = warp & 1;           // 0..1

    const __half* __restrict__ Mb = g_mid + (size_t)b * Cc * HW;

    float acc[4][4][4];
    #pragma unroll
    for (int i = 0; i < 4; i++)
        #pragma unroll
        for (int j = 0; j < 4; j++)
            #pragma unroll
            for (int q = 0; q < 4; q++) acc[i][j][q] = 0.0f;

    auto issue = [&](int st, int k0) {
        // A: 256 rows x 32 k = 1024 16B-chunks, 4 per thread
        #pragma unroll
        for (int i = 0; i < 4; i++) {
            int e = i * 256 + tid;
            int row = e >> 2, seg = e & 3;
            CP_ASYNC16(smem_u32(&sm[AS_OFF(st, row, seg * 8)]),
                       &g_wh[(size_t)row * 256 + k0 + seg * 8]);
        }
        // B: 32 rows x 64 n = 256 16B-chunks, 1 per thread
        {
            int row = tid >> 3, seg = tid & 7;
            CP_ASYNC16(smem_u32(&sm[BS_OFF(st, row, seg * 8)]),
                       &Mb[(size_t)(k0 + row) * HW + nBase + seg * 8]);
        }
    };

    issue(0, 0);
    CP_COMMIT();
    issue(1, 32);
    CP_COMMIT();

    for (int s = 0; s < 8; s++) {
        if (s < 7) {
            asm volatile("cp.async.wait_group 1;" ::: "memory");
        } else {
            asm volatile("cp.async.wait_group 0;" ::: "memory");
        }
        __syncthreads();

        const int st = s % 3;
        #pragma unroll
        for (int ks = 0; ks < 32; ks += 16) {
            u32 ah[4][4];
            const int a_m = warp_m * 64 + (lane & 15);
            const int a_k = ks + ((lane >> 4) << 3);
            #pragma unroll
            for (int fm = 0; fm < 4; fm++) {
                ldsm_x4(ah[fm][0], ah[fm][1], ah[fm][2], ah[fm][3],
                        smem_u32(&sm[AS_OFF(st, a_m + fm * 16, a_k)]));
            }
            u32 bq[4][2];
            const int b_k = ks + (lane & 15);
            const int b_n = warp_n * 32 + ((lane >> 4) << 3);
            #pragma unroll
            for (int g = 0; g < 2; g++) {
                u32 r0, r1, r2, r3;
                ldsm_x4t(r0, r1, r2, r3,
                         smem_u32(&sm[BS_OFF(st, b_k, b_n + g * 16)]));
                bq[g*2][0] = r0; bq[g*2][1] = r1;
                bq[g*2+1][0] = r2; bq[g*2+1][1] = r3;
            }
            #pragma unroll
            for (int fm = 0; fm < 4; fm++)
                #pragma unroll
                for (int fn = 0; fn < 4; fn++)
                    mma_f16(acc[fm][fn], ah[fm], bq[fn]);
        }

        if (s + 2 < 8) {
            issue((s + 2) % 3, (s + 2) * 32);
            CP_COMMIT();
        }
    }

    // Epilogue: pwbn (fp32) + ssq (fp32), stage fp16 tile (256 x 68-stride),
    // then coalesced stores (one warp per row, u32/lane = 128B rows).
    __syncthreads();
    __half* s_y = sm;  // 256 x 68 halves = 34816B < 75264B

    const int row  = lane >> 2;
    const int colq = (lane & 3) * 2;

    #pragma unroll
    for (int fm = 0; fm < 4; fm++) {
        const int o0 = warp_m * 64 + fm * 16 + row;
        const int o1 = o0 + 8;
        const float sc0 = pbw[o0] * rsqrtf(pbv[o0] + 1e-5f);
        const float sh0 = pbb[o0] - pbm[o0] * sc0;
        const float sc1 = pbw[o1] * rsqrtf(pbv[o1] + 1e-5f);
        const float sh1 = pbb[o1] - pbm[o1] * sc1;
        float ss0 = 0.0f, ss1 = 0.0f;
        #pragma unroll
        for (int fn = 0; fn < 4; fn++) {
            const int pl = warp_n * 32 + fn * 8 + colq;
            float v0 = acc[fm][fn][0] * sc0 + sh0;
            float v1 = acc[fm][fn][1] * sc0 + sh0;
            float v2 = acc[fm][fn][2] * sc1 + sh1;
            float v3 = acc[fm][fn][3] * sc1 + sh1;
            ss0 += v0 * v0 + v1 * v1;
            ss1 += v2 * v2 + v3 * v3;
            *(__half2*)&s_y[o0 * 68 + pl] =
                __halves2half2(__float2half(v0), __float2half(v1));
            *(__half2*)&s_y[o1 * 68 + pl] =
                __halves2half2(__float2half(v2), __float2half(v3));
        }
        ss0 += __shfl_xor_sync(0xffffffffu, ss0, 1);
        ss0 += __shfl_xor_sync(0xffffffffu, ss0, 2);
        ss1 += __shfl_xor_sync(0xffffffffu, ss1, 1);
        ss1 += __shfl_xor_sync(0xffffffffu, ss1, 2);
        if ((lane & 3) == 0) {
            atomicAdd(&g_ssq[b * Cc + o0], ss0);
            atomicAdd(&g_ssq[b * Cc + o1], ss1);
        }
    }
    __syncthreads();

    __half* __restrict__ yb = g_yh + (size_t)b * Cc * HW;
    #pragma unroll
    for (int k = 0; k < 32; k++) {
        const int r = warp + k * 8;          // 0..255
        u32 v = *(const u32*)&s_y[r * 68 + lane * 2];
        *(u32*)&yb[(size_t)r * HW + nBase + lane * 2] = v;
    }
}

// ---------------------------------------------------------------------------
// K4: fused GRN + final. One block per (b,c): reduce Gx over channels
// (redundant per block), then out = gelu(yh * a + beta[c] + x).
// ---------------------------------------------------------------------------
__global__ __launch_bounds__(256) void k_final(
    const float* __restrict__ x,
    const float* __restrict__ gamma,
    const float* __restrict__ beta,
    float* __restrict__ out)
{
    __shared__ float sh[256];

    const int bc = blockIdx.x;          // b*256 + c
    const int b  = bc >> 8;
    const int c  = bc & 255;
    const int tid = threadIdx.x;

    const float Gx_t = sqrtf(g_ssq[b * Cc + tid]);
    sh[tid] = Gx_t;
    __syncthreads();
    #pragma unroll
    for (int s = 128; s > 0; s >>= 1) {
        if (tid < s) sh[tid] += sh[tid + s];
        __syncthreads();
    }
    const float mean = sh[0] * (1.0f / 256.0f);
    const float Gx   = sqrtf(g_ssq[bc]);
    const float a    = 1.0f + gamma[c] * (Gx / (mean + 1e-6f));
    const float bt   = beta[c];

    const __half2* yp = (const __half2*)(g_yh + (size_t)bc * HW);
    const float4*  xp = (const float4*)(x + (size_t)bc * HW);
    float4*        op = (float4*)(out + (size_t)bc * HW);

    #pragma unroll
    for (int k = 0; k < 4; k++) {
        const int i4 = k * 256 + tid;
        __half2 y01 = yp[i4 * 2];
        __half2 y23 = yp[i4 * 2 + 1];
        float2 f01 = __half22float2(y01);
        float2 f23 = __half22float2(y23);
        float4 xv = xp[i4];
        float4 ov;
        ov.x = gelu_f(f01.x * a + bt + xv.x);
        ov.y = gelu_f(f01.y * a + bt + xv.y);
        ov.z = gelu_f(f23.x * a + bt + xv.z);
        ov.w = gelu_f(f23.y * a + bt + xv.w);
        op[i4] = ov;
    }
}

// ---------------------------------------------------------------------------
extern "C" void kernel_launch(void* const* d_in, const int* in_sizes, int n_in,
                              void* d_out, int out_size)
{
    const float* x    = (const float*)d_in[0];
    const float* w3   = (const float*)d_in[1];
    const float* b3w  = (const float*)d_in[2];
    const float* b3b  = (const float*)d_in[3];
    const float* b3m  = (const float*)d_in[4];
    const float* b3v  = (const float*)d_in[5];
    const float* w5   = (const float*)d_in[6];
    const float* b5w  = (const float*)d_in[7];
    const float* b5b  = (const float*)d_in[8];
    const float* b5m  = (const float*)d_in[9];
    const float* b5v  = (const float*)d_in[10];
    const float* w7   = (const float*)d_in[11];
    const float* b7w  = (const float*)d_in[12];
    const float* b7b  = (const float*)d_in[13];
    const float* b7m  = (const float*)d_in[14];
    const float* b7v  = (const float*)d_in[15];
    const float* pw   = (const float*)d_in[16];
    const float* pbw  = (const float*)d_in[17];
    const float* pbb  = (const float*)d_in[18];
    const float* pbm  = (const float*)d_in[19];
    const float* pbv  = (const float*)d_in[20];
    const float* grng = (const float*)d_in[21];
    const float* grnb = (const float*)d_in[22];

    cudaFuncSetAttribute(k_pwgemm,
                         cudaFuncAttributeMaxDynamicSharedMemorySize, K2_DYNSMEM);

    k_dwconv<<<Bb * Cc, 256>>>(x, w3, b3w, b3b, b3m, b3v,
                               w5, b5w, b5b, b5m, b5v,
                               w7, b7w, b7b, b7m, b7v, pw);

    dim3 g2(HW / 64, 1, Bb);   // (64, 1, 32)
    k_pwgemm<<<g2, 256, K2_DYNSMEM>>>(pbw, pbb, pbm, pbv);

    k_final<<<Bb * Cc, 256>>>(x, grng, grnb, (float*)d_out);
}

// round 15
// speedup vs baseline: 1.1876x; 1.1773x over previous
#include <cuda_runtime.h>
#include <cuda_fp16.h>
#include <stdint.h>
#include <math.h>

#define Bb 32
#define Cc 256
#define Hh 64
#define Ww 64
#define HW 4096
#define NTOT (Bb*Cc*HW)

typedef unsigned int u32;

// Scratch (allocation-free rule: __device__ globals)
__device__ __half g_mid[NTOT];         // 64 MB: dwconv output, fp16
__device__ __half g_wh[Cc*Cc];         // pointwise W, fp16
__device__ __half g_yh[NTOT];          // 64 MB: post-pointwise+pwbn, fp16
__device__ float g_ssq[Bb*Cc];         // per-(b,c) sum of squares

__device__ __forceinline__ float gelu_f(float v) {
    return 0.5f * v * (1.0f + erff(v * 0.7071067811865475f));
}

// Fast GELU: Abramowitz-Stegun 7.1.25 erf (3-term, |eps| <= 2.5e-5 abs).
__device__ __forceinline__ float gelu_fast(float v) {
    const float az = fabsf(v) * 0.7071067811865475f;
    const float t  = __fdividef(1.0f, fmaf(0.47047f, az, 1.0f));
    const float e  = __expf(-az * az);
    float p = fmaf(t, 0.7478556f, -0.0958798f);
    p = fmaf(t, p, 0.3480242f);
    p *= t;
    const float erfabs = fmaf(-p, e, 1.0f);
    return 0.5f * fmaf(fabsf(v), erfabs, v);
}

__device__ __forceinline__ u32 smem_u32(const void* p) {
    return (u32)__cvta_generic_to_shared(p);
}

__device__ __forceinline__ void ldsm_x4(u32& r0, u32& r1, u32& r2, u32& r3, u32 a) {
    asm volatile("ldmatrix.sync.aligned.m8n8.x4.shared.b16 {%0,%1,%2,%3},[%4];\n"
                 : "=r"(r0), "=r"(r1), "=r"(r2), "=r"(r3) : "r"(a));
}
__device__ __forceinline__ void ldsm_x4t(u32& r0, u32& r1, u32& r2, u32& r3, u32 a) {
    asm volatile("ldmatrix.sync.aligned.m8n8.x4.trans.shared.b16 {%0,%1,%2,%3},[%4];\n"
                 : "=r"(r0), "=r"(r1), "=r"(r2), "=r"(r3) : "r"(a));
}
__device__ __forceinline__ void mma_f16(float* c, const u32* a, const u32* bq) {
    asm volatile(
        "mma.sync.aligned.m16n8k16.row.col.f32.f16.f16.f32 "
        "{%0,%1,%2,%3},{%4,%5,%6,%7},{%8,%9},{%0,%1,%2,%3};\n"
        : "+f"(c[0]), "+f"(c[1]), "+f"(c[2]), "+f"(c[3])
        : "r"(a[0]), "r"(a[1]), "r"(a[2]), "r"(a[3]), "r"(bq[0]), "r"(bq[1]));
}

#define CP_ASYNC16(dst, src) \
    asm volatile("cp.async.cg.shared.global [%0], [%1], 16;" :: "r"(dst), "l"(src))
#define CP_COMMIT() asm volatile("cp.async.commit_group;" ::: "memory")

// ---------------------------------------------------------------------------
// K1: fused dwconv(3,5,7) + BN + GELU + average -> g_mid (fp16)
// R12 structure + __launch_bounds__(256,5): cap regs ~51 to lift occupancy
// from 4 to 5 CTAs/SM (issue-limited kernel, exposed LDS latency).
// ---------------------------------------------------------------------------
__global__ __launch_bounds__(256, 5) void k_dwconv(
    const float* __restrict__ x,
    const float* __restrict__ w3,
    const float* __restrict__ b3w, const float* __restrict__ b3b,
    const float* __restrict__ b3m, const float* __restrict__ b3v,
    const float* __restrict__ w5,
    const float* __restrict__ b5w, const float* __restrict__ b5b,
    const float* __restrict__ b5m, const float* __restrict__ b5v,
    const float* __restrict__ w7,
    const float* __restrict__ b7w, const float* __restrict__ b7b,
    const float* __restrict__ b7m, const float* __restrict__ b7v,
    const float* __restrict__ pw)
{
    __shared__ float tile[70 * 72];
    __shared__ float sw3[9], sw5[25], sw7[49];

    const int blk = blockIdx.x;        // b*256 + c
    const int c   = blk & 255;
    const int tid = threadIdx.x;

    if (tid == 0) g_ssq[blk] = 0.0f;

    if (blk < 256) {
        int i = blk * 256 + tid;
        g_wh[i] = __float2half(pw[i]);
    }

    const float* __restrict__ xp = x + (size_t)blk * HW;

    if (tid < 9)        sw3[tid]      = w3[c * 9 + tid];
    else if (tid < 34)  sw5[tid - 9]  = w5[c * 25 + (tid - 9)];
    else if (tid < 83)  sw7[tid - 34] = w7[c * 49 + (tid - 34)];

    for (int idx = tid; idx < 70 * 70; idx += 256) {
        int sy = idx / 70, sx = idx - sy * 70;
        int gy = sy - 3, gx = sx - 3;
        float v = 0.0f;
        if ((unsigned)gy < 64u && (unsigned)gx < 64u) v = xp[gy * 64 + gx];
        tile[sy * 72 + sx] = v;
    }

    const float sc3 = b3w[c] * rsqrtf(b3v[c] + 1e-5f);
    const float sh3 = b3b[c] - b3m[c] * sc3;
    const float sc5 = b5w[c] * rsqrtf(b5v[c] + 1e-5f);
    const float sh5 = b5b[c] - b5m[c] * sc5;
    const float sc7 = b7w[c] * rsqrtf(b7v[c] + 1e-5f);
    const float sh7 = b7b[c] - b7m[c] * sc7;

    __syncthreads();

    const int tx = tid & 15;
    const int r0 = tid >> 4;
    const float inv3 = (1.0f / 3.0f);

    #pragma unroll
    for (int rit = 0; rit < 4; rit++) {
        const int y = r0 + rit * 16;
        float a3[4] = {0.f, 0.f, 0.f, 0.f};
        float a5[4] = {0.f, 0.f, 0.f, 0.f};
        float a7[4] = {0.f, 0.f, 0.f, 0.f};

        #pragma unroll
        for (int ky = 0; ky < 7; ky++) {
            const float* rowp = &tile[(y + ky) * 72 + tx * 4];
            float4 v0 = *(const float4*)(rowp);
            float4 v1 = *(const float4*)(rowp + 4);
            float4 v2 = *(const float4*)(rowp + 8);
            float f[12];
            f[0]=v0.x; f[1]=v0.y; f[2]=v0.z; f[3]=v0.w;
            f[4]=v1.x; f[5]=v1.y; f[6]=v1.z; f[7]=v1.w;
            f[8]=v2.x; f[9]=v2.y; f[10]=v2.z; f[11]=v2.w;

            #pragma unroll
            for (int kx = 0; kx < 7; kx++) {
                const float w = sw7[ky * 7 + kx];
                #pragma unroll
                for (int j = 0; j < 4; j++) a7[j] += f[j + kx] * w;
            }
            if (ky >= 1 && ky <= 5) {
                #pragma unroll
                for (int kx = 0; kx < 5; kx++) {
                    const float w = sw5[(ky - 1) * 5 + kx];
                    #pragma unroll
                    for (int j = 0; j < 4; j++) a5[j] += f[j + 1 + kx] * w;
                }
            }
            if (ky >= 2 && ky <= 4) {
                #pragma unroll
                for (int kx = 0; kx < 3; kx++) {
                    const float w = sw3[(ky - 2) * 3 + kx];
                    #pragma unroll
                    for (int j = 0; j < 4; j++) a3[j] += f[j + 2 + kx] * w;
                }
            }
        }

        __half hh[4];
        #pragma unroll
        for (int j = 0; j < 4; j++) {
            float v = gelu_fast(a3[j] * sc3 + sh3)
                    + gelu_fast(a5[j] * sc5 + sh5)
                    + gelu_fast(a7[j] * sc7 + sh7);
            hh[j] = __float2half(v * inv3);
        }
        size_t off = (size_t)blk * HW + y * 64 + tx * 4;
        ((__half2*)&g_mid[off])[0] = __halves2half2(hh[0], hh[1]);
        ((__half2*)&g_mid[off])[1] = __halves2half2(hh[2], hh[3]);
    }
}

// ---------------------------------------------------------------------------
// K2: mma.sync fp16 GEMM, single term, 3-stage cp.async pipeline.
// Block tile 128(M=o) x 128(N=p), BK=32. 8 warps: 2(M) x 4(N).
// Fused pwbn + ssq; smem-staged coalesced fp16 y stores. (R12 version)
// ---------------------------------------------------------------------------
#define AS_OFF(st, m, k) ((st) * (128*40) + (m)*40 + (k))
#define BS_OFF(st, k, n) (15360 + (st)*(32*136) + (k)*136 + (n))
#define K2_DYNSMEM ((15360 + 13056) * 2)

__global__ __launch_bounds__(256) void k_pwgemm(
    const float* __restrict__ pbw, const float* __restrict__ pbb,
    const float* __restrict__ pbm, const float* __restrict__ pbv)
{
    extern __shared__ __half sm[];

    const int b     = blockIdx.z;
    const int nBase = blockIdx.x * 128;
    const int mBase = blockIdx.y * 128;

    const int tid  = threadIdx.x;
    const int lane = tid & 31;
    const int warp = tid >> 5;
    const int warp_m = warp >> 2;
    const int warp_n = warp & 3;

    const __half* __restrict__ Mb = g_mid + (size_t)b * Cc * HW;

    float acc[4][4][4];
    #pragma unroll
    for (int i = 0; i < 4; i++)
        #pragma unroll
        for (int j = 0; j < 4; j++)
            #pragma unroll
            for (int q = 0; q < 4; q++) acc[i][j][q] = 0.0f;

    auto issue = [&](int st, int k0) {
        #pragma unroll
        for (int i = 0; i < 2; i++) {
            int e = i * 256 + tid;
            int row = e >> 2, seg = e & 3;
            CP_ASYNC16(smem_u32(&sm[AS_OFF(st, row, seg * 8)]),
                       &g_wh[(size_t)(mBase + row) * 256 + k0 + seg * 8]);
        }
        #pragma unroll
        for (int i = 0; i < 2; i++) {
            int e = i * 256 + tid;
            int row = e >> 4, seg = e & 15;
            CP_ASYNC16(smem_u32(&sm[BS_OFF(st, row, seg * 8)]),
                       &Mb[(size_t)(k0 + row) * HW + nBase + seg * 8]);
        }
    };

    issue(0, 0);
    CP_COMMIT();
    issue(1, 32);
    CP_COMMIT();

    for (int s = 0; s < 8; s++) {
        if (s < 7) {
            asm volatile("cp.async.wait_group 1;" ::: "memory");
        } else {
            asm volatile("cp.async.wait_group 0;" ::: "memory");
        }
        __syncthreads();

        const int st = s % 3;
        #pragma unroll
        for (int ks = 0; ks < 32; ks += 16) {
            u32 ah[4][4];
            const int a_m = warp_m * 64 + (lane & 15);
            const int a_k = ks + ((lane >> 4) << 3);
            #pragma unroll
            for (int fm = 0; fm < 4; fm++) {
                ldsm_x4(ah[fm][0], ah[fm][1], ah[fm][2], ah[fm][3],
                        smem_u32(&sm[AS_OFF(st, a_m + fm * 16, a_k)]));
            }
            u32 bq[4][2];
            const int b_k = ks + (lane & 15);
            const int b_n = warp_n * 32 + ((lane >> 4) << 3);
            #pragma unroll
            for (int g = 0; g < 2; g++) {
                u32 r0, r1, r2, r3;
                ldsm_x4t(r0, r1, r2, r3,
                         smem_u32(&sm[BS_OFF(st, b_k, b_n + g * 16)]));
                bq[g*2][0] = r0; bq[g*2][1] = r1;
                bq[g*2+1][0] = r2; bq[g*2+1][1] = r3;
            }
            #pragma unroll
            for (int fm = 0; fm < 4; fm++)
                #pragma unroll
                for (int fn = 0; fn < 4; fn++)
                    mma_f16(acc[fm][fn], ah[fm], bq[fn]);
        }

        if (s + 2 < 8) {
            issue((s + 2) % 3, (s + 2) * 32);
            CP_COMMIT();
        }
    }

    __syncthreads();
    __half* s_y = sm;  // 128 x 136 halves

    const int row  = lane >> 2;
    const int colq = (lane & 3) * 2;

    #pragma unroll
    for (int fm = 0; fm < 4; fm++) {
        const int o0 = mBase + warp_m * 64 + fm * 16 + row;
        const int o1 = o0 + 8;
        const int l0 = warp_m * 64 + fm * 16 + row;
        const float sc0 = pbw[o0] * rsqrtf(pbv[o0] + 1e-5f);
        const float sh0 = pbb[o0] - pbm[o0] * sc0;
        const float sc1 = pbw[o1] * rsqrtf(pbv[o1] + 1e-5f);
        const float sh1 = pbb[o1] - pbm[o1] * sc1;
        float ss0 = 0.0f, ss1 = 0.0f;
        #pragma unroll
        for (int fn = 0; fn < 4; fn++) {
            const int pl = warp_n * 32 + fn * 8 + colq;
            float v0 = acc[fm][fn][0] * sc0 + sh0;
            float v1 = acc[fm][fn][1] * sc0 + sh0;
            float v2 = acc[fm][fn][2] * sc1 + sh1;
            float v3 = acc[fm][fn][3] * sc1 + sh1;
            ss0 += v0 * v0 + v1 * v1;
            ss1 += v2 * v2 + v3 * v3;
            *(__half2*)&s_y[l0 * 136 + pl] =
                __halves2half2(__float2half(v0), __float2half(v1));
            *(__half2*)&s_y[(l0 + 8) * 136 + pl] =
                __halves2half2(__float2half(v2), __float2half(v3));
        }
        ss0 += __shfl_xor_sync(0xffffffffu, ss0, 1);
        ss0 += __shfl_xor_sync(0xffffffffu, ss0, 2);
        ss1 += __shfl_xor_sync(0xffffffffu, ss1, 1);
        ss1 += __shfl_xor_sync(0xffffffffu, ss1, 2);
        if ((lane & 3) == 0) {
            atomicAdd(&g_ssq[b * Cc + o0], ss0);
            atomicAdd(&g_ssq[b * Cc + o1], ss1);
        }
    }
    __syncthreads();

    __half* __restrict__ yb = g_yh + (size_t)b * Cc * HW;
    #pragma unroll
    for (int k = 0; k < 16; k++) {
        const int r = warp + k * 8;
        uint2 v = *(const uint2*)&s_y[r * 136 + lane * 4];
        *(uint2*)&yb[(size_t)(mBase + r) * HW + nBase + lane * 4] = v;
    }
}

// ---------------------------------------------------------------------------
// K4: fused GRN + final. One block per (b,c): reduce Gx over channels
// (redundant per block), then out = gelu(yh * a + beta[c] + x).
// ---------------------------------------------------------------------------
__global__ __launch_bounds__(256) void k_final(
    const float* __restrict__ x,
    const float* __restrict__ gamma,
    const float* __restrict__ beta,
    float* __restrict__ out)
{
    __shared__ float sh[256];

    const int bc = blockIdx.x;          // b*256 + c
    const int b  = bc >> 8;
    const int c  = bc & 255;
    const int tid = threadIdx.x;

    const float Gx_t = sqrtf(g_ssq[b * Cc + tid]);
    sh[tid] = Gx_t;
    __syncthreads();
    #pragma unroll
    for (int s = 128; s > 0; s >>= 1) {
        if (tid < s) sh[tid] += sh[tid + s];
        __syncthreads();
    }
    const float mean = sh[0] * (1.0f / 256.0f);
    const float Gx   = sqrtf(g_ssq[bc]);
    const float a    = 1.0f + gamma[c] * (Gx / (mean + 1e-6f));
    const float bt   = beta[c];

    const __half2* yp = (const __half2*)(g_yh + (size_t)bc * HW);
    const float4*  xp = (const float4*)(x + (size_t)bc * HW);
    float4*        op = (float4*)(out + (size_t)bc * HW);

    #pragma unroll
    for (int k = 0; k < 4; k++) {
        const int i4 = k * 256 + tid;
        __half2 y01 = yp[i4 * 2];
        __half2 y23 = yp[i4 * 2 + 1];
        float2 f01 = __half22float2(y01);
        float2 f23 = __half22float2(y23);
        float4 xv = xp[i4];
        float4 ov;
        ov.x = gelu_f(f01.x * a + bt + xv.x);
        ov.y = gelu_f(f01.y * a + bt + xv.y);
        ov.z = gelu_f(f23.x * a + bt + xv.z);
        ov.w = gelu_f(f23.y * a + bt + xv.w);
        op[i4] = ov;
    }
}

// ---------------------------------------------------------------------------
extern "C" void kernel_launch(void* const* d_in, const int* in_sizes, int n_in,
                              void* d_out, int out_size)
{
    const float* x    = (const float*)d_in[0];
    const float* w3   = (const float*)d_in[1];
    const float* b3w  = (const float*)d_in[2];
    const float* b3b  = (const float*)d_in[3];
    const float* b3m  = (const float*)d_in[4];
    const float* b3v  = (const float*)d_in[5];
    const float* w5   = (const float*)d_in[6];
    const float* b5w  = (const float*)d_in[7];
    const float* b5b  = (const float*)d_in[8];
    const float* b5m  = (const float*)d_in[9];
    const float* b5v  = (const float*)d_in[10];
    const float* w7   = (const float*)d_in[11];
    const float* b7w  = (const float*)d_in[12];
    const float* b7b  = (const float*)d_in[13];
    const float* b7m  = (const float*)d_in[14];
    const float* b7v  = (const float*)d_in[15];
    const float* pw   = (const float*)d_in[16];
    const float* pbw  = (const float*)d_in[17];
    const float* pbb  = (const float*)d_in[18];
    const float* pbm  = (const float*)d_in[19];
    const float* pbv  = (const float*)d_in[20];
    const float* grng = (const float*)d_in[21];
    const float* grnb = (const float*)d_in[22];

    cudaFuncSetAttribute(k_pwgemm,
                         cudaFuncAttributeMaxDynamicSharedMemorySize, K2_DYNSMEM);

    k_dwconv<<<Bb * Cc, 256>>>(x, w3, b3w, b3b, b3m, b3v,
                               w5, b5w, b5b, b5m, b5v,
                               w7, b7w, b7b, b7m, b7v, pw);

    dim3 g2(HW / 128, Cc / 128, Bb);   // (32, 2, 32)
    k_pwgemm<<<g2, 256, K2_DYNSMEM>>>(pbw, pbb, pbm, pbv);

    k_final<<<Bb * Cc, 256>>>(x, grng, grnb, (float*)d_out);
}

// round 16
// speedup vs baseline: 1.2318x; 1.0372x over previous
#include <cuda_runtime.h>
#include <cuda_fp16.h>
#include <stdint.h>
#include <math.h>

#define Bb 32
#define Cc 256
#define Hh 64
#define Ww 64
#define HW 4096
#define NTOT (Bb*Cc*HW)

typedef unsigned int u32;

// Scratch (allocation-free rule: __device__ globals)
__device__ __half g_mid[NTOT];         // 64 MB: dwconv output, fp16
__device__ __half g_wh[Cc*Cc];         // pointwise W, fp16
__device__ __half g_yh[NTOT];          // 64 MB: post-pointwise+pwbn, fp16
__device__ float g_ssq[Bb*Cc];         // per-(b,c) sum of squares

__device__ __forceinline__ float gelu_f(float v) {
    return 0.5f * v * (1.0f + erff(v * 0.7071067811865475f));
}

// Fast GELU: Abramowitz-Stegun 7.1.25 erf (3-term, |eps| <= 2.5e-5 abs).
__device__ __forceinline__ float gelu_fast(float v) {
    const float az = fabsf(v) * 0.7071067811865475f;
    const float t  = __fdividef(1.0f, fmaf(0.47047f, az, 1.0f));
    const float e  = __expf(-az * az);
    float p = fmaf(t, 0.7478556f, -0.0958798f);
    p = fmaf(t, p, 0.3480242f);
    p *= t;
    const float erfabs = fmaf(-p, e, 1.0f);
    return 0.5f * fmaf(fabsf(v), erfabs, v);
}

__device__ __forceinline__ u32 smem_u32(const void* p) {
    return (u32)__cvta_generic_to_shared(p);
}

__device__ __forceinline__ void ldsm_x4(u32& r0, u32& r1, u32& r2, u32& r3, u32 a) {
    asm volatile("ldmatrix.sync.aligned.m8n8.x4.shared.b16 {%0,%1,%2,%3},[%4];\n"
                 : "=r"(r0), "=r"(r1), "=r"(r2), "=r"(r3) : "r"(a));
}
__device__ __forceinline__ void ldsm_x4t(u32& r0, u32& r1, u32& r2, u32& r3, u32 a) {
    asm volatile("ldmatrix.sync.aligned.m8n8.x4.trans.shared.b16 {%0,%1,%2,%3},[%4];\n"
                 : "=r"(r0), "=r"(r1), "=r"(r2), "=r"(r3) : "r"(a));
}
__device__ __forceinline__ void mma_f16(float* c, const u32* a, const u32* bq) {
    asm volatile(
        "mma.sync.aligned.m16n8k16.row.col.f32.f16.f16.f32 "
        "{%0,%1,%2,%3},{%4,%5,%6,%7},{%8,%9},{%0,%1,%2,%3};\n"
        : "+f"(c[0]), "+f"(c[1]), "+f"(c[2]), "+f"(c[3])
        : "r"(a[0]), "r"(a[1]), "r"(a[2]), "r"(a[3]), "r"(bq[0]), "r"(bq[1]));
}

#define CP_ASYNC16(dst, src) \
    asm volatile("cp.async.cg.shared.global [%0], [%1], 16;" :: "r"(dst), "l"(src))
#define CP_COMMIT() asm volatile("cp.async.commit_group;" ::: "memory")

// ---------------------------------------------------------------------------
// K1: fused dwconv(3,5,7) + BN + GELU + average -> g_mid (fp16)
// R15 structure, pushed to __launch_bounds__(256,6): regs capped ~42 to lift
// occupancy from 5 to 6 CTAs/SM. Base-pointer increments replace per-row IMADs.
// ---------------------------------------------------------------------------
__global__ __launch_bounds__(256, 6) void k_dwconv(
    const float* __restrict__ x,
    const float* __restrict__ w3,
    const float* __restrict__ b3w, const float* __restrict__ b3b,
    const float* __restrict__ b3m, const float* __restrict__ b3v,
    const float* __restrict__ w5,
    const float* __restrict__ b5w, const float* __restrict__ b5b,
    const float* __restrict__ b5m, const float* __restrict__ b5v,
    const float* __restrict__ w7,
    const float* __restrict__ b7w, const float* __restrict__ b7b,
    const float* __restrict__ b7m, const float* __restrict__ b7v,
    const float* __restrict__ pw)
{
    __shared__ float tile[70 * 72];
    __shared__ float sw3[9], sw5[25], sw7[49];

    const int blk = blockIdx.x;        // b*256 + c
    const int c   = blk & 255;
    const int tid = threadIdx.x;

    if (tid == 0) g_ssq[blk] = 0.0f;

    if (blk < 256) {
        int i = blk * 256 + tid;
        g_wh[i] = __float2half(pw[i]);
    }

    const float* __restrict__ xp = x + (size_t)blk * HW;

    if (tid < 9)        sw3[tid]      = w3[c * 9 + tid];
    else if (tid < 34)  sw5[tid - 9]  = w5[c * 25 + (tid - 9)];
    else if (tid < 83)  sw7[tid - 34] = w7[c * 49 + (tid - 34)];

    for (int idx = tid; idx < 70 * 70; idx += 256) {
        int sy = idx / 70, sx = idx - sy * 70;
        int gy = sy - 3, gx = sx - 3;
        float v = 0.0f;
        if ((unsigned)gy < 64u && (unsigned)gx < 64u) v = xp[gy * 64 + gx];
        tile[sy * 72 + sx] = v;
    }

    const float sc3 = b3w[c] * rsqrtf(b3v[c] + 1e-5f);
    const float sh3 = b3b[c] - b3m[c] * sc3;
    const float sc5 = b5w[c] * rsqrtf(b5v[c] + 1e-5f);
    const float sh5 = b5b[c] - b5m[c] * sc5;
    const float sc7 = b7w[c] * rsqrtf(b7v[c] + 1e-5f);
    const float sh7 = b7b[c] - b7m[c] * sc7;

    __syncthreads();

    const int tx = tid & 15;
    const int r0 = tid >> 4;
    const float inv3 = (1.0f / 3.0f);

    #pragma unroll
    for (int rit = 0; rit < 4; rit++) {
        const int y = r0 + rit * 16;
        float a3[4] = {0.f, 0.f, 0.f, 0.f};
        float a5[4] = {0.f, 0.f, 0.f, 0.f};
        float a7[4] = {0.f, 0.f, 0.f, 0.f};

        const float* rowp = &tile[y * 72 + tx * 4];
        #pragma unroll
        for (int ky = 0; ky < 7; ky++, rowp += 72) {
            float4 v0 = *(const float4*)(rowp);
            float4 v1 = *(const float4*)(rowp + 4);
            float4 v2 = *(const float4*)(rowp + 8);
            float f[12];
            f[0]=v0.x; f[1]=v0.y; f[2]=v0.z; f[3]=v0.w;
            f[4]=v1.x; f[5]=v1.y; f[6]=v1.z; f[7]=v1.w;
            f[8]=v2.x; f[9]=v2.y; f[10]=v2.z; f[11]=v2.w;

            #pragma unroll
            for (int kx = 0; kx < 7; kx++) {
                const float w = sw7[ky * 7 + kx];
                #pragma unroll
                for (int j = 0; j < 4; j++) a7[j] += f[j + kx] * w;
            }
            if (ky >= 1 && ky <= 5) {
                #pragma unroll
                for (int kx = 0; kx < 5; kx++) {
                    const float w = sw5[(ky - 1) * 5 + kx];
                    #pragma unroll
                    for (int j = 0; j < 4; j++) a5[j] += f[j + 1 + kx] * w;
                }
            }
            if (ky >= 2 && ky <= 4) {
                #pragma unroll
                for (int kx = 0; kx < 3; kx++) {
                    const float w = sw3[(ky - 2) * 3 + kx];
                    #pragma unroll
                    for (int j = 0; j < 4; j++) a3[j] += f[j + 2 + kx] * w;
                }
            }
        }

        __half hh[4];
        #pragma unroll
        for (int j = 0; j < 4; j++) {
            float v = gelu_fast(a3[j] * sc3 + sh3)
                    + gelu_fast(a5[j] * sc5 + sh5)
                    + gelu_fast(a7[j] * sc7 + sh7);
            hh[j] = __float2half(v * inv3);
        }
        size_t off = (size_t)blk * HW + y * 64 + tx * 4;
        ((__half2*)&g_mid[off])[0] = __halves2half2(hh[0], hh[1]);
        ((__half2*)&g_mid[off])[1] = __halves2half2(hh[2], hh[3]);
    }
}

// ---------------------------------------------------------------------------
// K2: mma.sync fp16 GEMM, single term, 3-stage cp.async pipeline.
// Block tile 128(M=o) x 128(N=p), BK=32. 8 warps: 2(M) x 4(N).
// Fused pwbn + ssq; smem-staged coalesced fp16 y stores. (R12/R15 version)
// ---------------------------------------------------------------------------
#define AS_OFF(st, m, k) ((st) * (128*40) + (m)*40 + (k))
#define BS_OFF(st, k, n) (15360 + (st)*(32*136) + (k)*136 + (n))
#define K2_DYNSMEM ((15360 + 13056) * 2)

__global__ __launch_bounds__(256) void k_pwgemm(
    const float* __restrict__ pbw, const float* __restrict__ pbb,
    const float* __restrict__ pbm, const float* __restrict__ pbv)
{
    extern __shared__ __half sm[];

    const int b     = blockIdx.z;
    const int nBase = blockIdx.x * 128;
    const int mBase = blockIdx.y * 128;

    const int tid  = threadIdx.x;
    const int lane = tid & 31;
    const int warp = tid >> 5;
    const int warp_m = warp >> 2;
    const int warp_n = warp & 3;

    const __half* __restrict__ Mb = g_mid + (size_t)b * Cc * HW;

    float acc[4][4][4];
    #pragma unroll
    for (int i = 0; i < 4; i++)
        #pragma unroll
        for (int j = 0; j < 4; j++)
            #pragma unroll
            for (int q = 0; q < 4; q++) acc[i][j][q] = 0.0f;

    auto issue = [&](int st, int k0) {
        #pragma unroll
        for (int i = 0; i < 2; i++) {
            int e = i * 256 + tid;
            int row = e >> 2, seg = e & 3;
            CP_ASYNC16(smem_u32(&sm[AS_OFF(st, row, seg * 8)]),
                       &g_wh[(size_t)(mBase + row) * 256 + k0 + seg * 8]);
        }
        #pragma unroll
        for (int i = 0; i < 2; i++) {
            int e = i * 256 + tid;
            int row = e >> 4, seg = e & 15;
            CP_ASYNC16(smem_u32(&sm[BS_OFF(st, row, seg * 8)]),
                       &Mb[(size_t)(k0 + row) * HW + nBase + seg * 8]);
        }
    };

    issue(0, 0);
    CP_COMMIT();
    issue(1, 32);
    CP_COMMIT();

    for (int s = 0; s < 8; s++) {
        if (s < 7) {
            asm volatile("cp.async.wait_group 1;" ::: "memory");
        } else {
            asm volatile("cp.async.wait_group 0;" ::: "memory");
        }
        __syncthreads();

        const int st = s % 3;
        #pragma unroll
        for (int ks = 0; ks < 32; ks += 16) {
            u32 ah[4][4];
            const int a_m = warp_m * 64 + (lane & 15);
            const int a_k = ks + ((lane >> 4) << 3);
            #pragma unroll
            for (int fm = 0; fm < 4; fm++) {
                ldsm_x4(ah[fm][0], ah[fm][1], ah[fm][2], ah[fm][3],
                        smem_u32(&sm[AS_OFF(st, a_m + fm * 16, a_k)]));
            }
            u32 bq[4][2];
            const int b_k = ks + (lane & 15);
            const int b_n = warp_n * 32 + ((lane >> 4) << 3);
            #pragma unroll
            for (int g = 0; g < 2; g++) {
                u32 r0, r1, r2, r3;
                ldsm_x4t(r0, r1, r2, r3,
                         smem_u32(&sm[BS_OFF(st, b_k, b_n + g * 16)]));
                bq[g*2][0] = r0; bq[g*2][1] = r1;
                bq[g*2+1][0] = r2; bq[g*2+1][1] = r3;
            }
            #pragma unroll
            for (int fm = 0; fm < 4; fm++)
                #pragma unroll
                for (int fn = 0; fn < 4; fn++)
                    mma_f16(acc[fm][fn], ah[fm], bq[fn]);
        }

        if (s + 2 < 8) {
            issue((s + 2) % 3, (s + 2) * 32);
            CP_COMMIT();
        }
    }

    __syncthreads();
    __half* s_y = sm;  // 128 x 136 halves

    const int row  = lane >> 2;
    const int colq = (lane & 3) * 2;

    #pragma unroll
    for (int fm = 0; fm < 4; fm++) {
        const int o0 = mBase + warp_m * 64 + fm * 16 + row;
        const int o1 = o0 + 8;
        const int l0 = warp_m * 64 + fm * 16 + row;
        const float sc0 = pbw[o0] * rsqrtf(pbv[o0] + 1e-5f);
        const float sh0 = pbb[o0] - pbm[o0] * sc0;
        const float sc1 = pbw[o1] * rsqrtf(pbv[o1] + 1e-5f);
        const float sh1 = pbb[o1] - pbm[o1] * sc1;
        float ss0 = 0.0f, ss1 = 0.0f;
        #pragma unroll
        for (int fn = 0; fn < 4; fn++) {
            const int pl = warp_n * 32 + fn * 8 + colq;
            float v0 = acc[fm][fn][0] * sc0 + sh0;
            float v1 = acc[fm][fn][1] * sc0 + sh0;
            float v2 = acc[fm][fn][2] * sc1 + sh1;
            float v3 = acc[fm][fn][3] * sc1 + sh1;
            ss0 += v0 * v0 + v1 * v1;
            ss1 += v2 * v2 + v3 * v3;
            *(__half2*)&s_y[l0 * 136 + pl] =
                __halves2half2(__float2half(v0), __float2half(v1));
            *(__half2*)&s_y[(l0 + 8) * 136 + pl] =
                __halves2half2(__float2half(v2), __float2half(v3));
        }
        ss0 += __shfl_xor_sync(0xffffffffu, ss0, 1);
        ss0 += __shfl_xor_sync(0xffffffffu, ss0, 2);
        ss1 += __shfl_xor_sync(0xffffffffu, ss1, 1);
        ss1 += __shfl_xor_sync(0xffffffffu, ss1, 2);
        if ((lane & 3) == 0) {
            atomicAdd(&g_ssq[b * Cc + o0], ss0);
            atomicAdd(&g_ssq[b * Cc + o1], ss1);
        }
    }
    __syncthreads();

    __half* __restrict__ yb = g_yh + (size_t)b * Cc * HW;
    #pragma unroll
    for (int k = 0; k < 16; k++) {
        const int r = warp + k * 8;
        uint2 v = *(const uint2*)&s_y[r * 136 + lane * 4];
        *(uint2*)&yb[(size_t)(mBase + r) * HW + nBase + lane * 4] = v;
    }
}

// ---------------------------------------------------------------------------
// K4: fused GRN + final. One block per (b,c): reduce Gx over channels
// (redundant per block), then out = gelu(yh * a + beta[c] + x).
// ---------------------------------------------------------------------------
__global__ __launch_bounds__(256) void k_final(
    const float* __restrict__ x,
    const float* __restrict__ gamma,
    const float* __restrict__ beta,
    float* __restrict__ out)
{
    __shared__ float sh[256];

    const int bc = blockIdx.x;          // b*256 + c
    const int b  = bc >> 8;
    const int c  = bc & 255;
    const int tid = threadIdx.x;

    const float Gx_t = sqrtf(g_ssq[b * Cc + tid]);
    sh[tid] = Gx_t;
    __syncthreads();
    #pragma unroll
    for (int s = 128; s > 0; s >>= 1) {
        if (tid < s) sh[tid] += sh[tid + s];
        __syncthreads();
    }
    const float mean = sh[0] * (1.0f / 256.0f);
    const float Gx   = sqrtf(g_ssq[bc]);
    const float a    = 1.0f + gamma[c] * (Gx / (mean + 1e-6f));
    const float bt   = beta[c];

    const __half2* yp = (const __half2*)(g_yh + (size_t)bc * HW);
    const float4*  xp = (const float4*)(x + (size_t)bc * HW);
    float4*        op = (float4*)(out + (size_t)bc * HW);

    #pragma unroll
    for (int k = 0; k < 4; k++) {
        const int i4 = k * 256 + tid;
        __half2 y01 = yp[i4 * 2];
        __half2 y23 = yp[i4 * 2 + 1];
        float2 f01 = __half22float2(y01);
        float2 f23 = __half22float2(y23);
        float4 xv = xp[i4];
        float4 ov;
        ov.x = gelu_f(f01.x * a + bt + xv.x);
        ov.y = gelu_f(f01.y * a + bt + xv.y);
        ov.z = gelu_f(f23.x * a + bt + xv.z);
        ov.w = gelu_f(f23.y * a + bt + xv.w);
        op[i4] = ov;
    }
}

// ---------------------------------------------------------------------------
extern "C" void kernel_launch(void* const* d_in, const int* in_sizes, int n_in,
                              void* d_out, int out_size)
{
    const float* x    = (const float*)d_in[0];
    const float* w3   = (const float*)d_in[1];
    const float* b3w  = (const float*)d_in[2];
    const float* b3b  = (const float*)d_in[3];
    const float* b3m  = (const float*)d_in[4];
    const float* b3v  = (const float*)d_in[5];
    const float* w5   = (const float*)d_in[6];
    const float* b5w  = (const float*)d_in[7];
    const float* b5b  = (const float*)d_in[8];
    const float* b5m  = (const float*)d_in[9];
    const float* b5v  = (const float*)d_in[10];
    const float* w7   = (const float*)d_in[11];
    const float* b7w  = (const float*)d_in[12];
    const float* b7b  = (const float*)d_in[13];
    const float* b7m  = (const float*)d_in[14];
    const float* b7v  = (const float*)d_in[15];
    const float* pw   = (const float*)d_in[16];
    const float* pbw  = (const float*)d_in[17];
    const float* pbb  = (const float*)d_in[18];
    const float* pbm  = (const float*)d_in[19];
    const float* pbv  = (const float*)d_in[20];
    const float* grng = (const float*)d_in[21];
    const float* grnb = (const float*)d_in[22];

    cudaFuncSetAttribute(k_pwgemm,
                         cudaFuncAttributeMaxDynamicSharedMemorySize, K2_DYNSMEM);

    k_dwconv<<<Bb * Cc, 256>>>(x, w3, b3w, b3b, b3m, b3v,
                               w5, b5w, b5b, b5m, b5v,
                               w7, b7w, b7b, b7m, b7v, pw);

    dim3 g2(HW / 128, Cc / 128, Bb);   // (32, 2, 32)
    k_pwgemm<<<g2, 256, K2_DYNSMEM>>>(pbw, pbb, pbm, pbv);

    k_final<<<Bb * Cc, 256>>>(x, grng, grnb, (float*)d_out);
}